// round 3
// baseline (speedup 1.0000x reference)
#include <cuda_runtime.h>
#include <math_constants.h>
#include <cstdint>
#include <cstddef>

// ---------------- problem constants ----------------
#define NB    128          // batch (events)
#define NV    1024         // vertices per event
#define NFEAT 10           // input features
#define NBK   11           // GarNet blocks
#define NF    32           // filters
#define NP    20           // propagate
#define NA    4            // aggregators
#define NC    24           // NP + NA (feat dim)
#define DFE   352          // NBK * NF
#define TPB1  512
#define K2_T  256

// global scratch: block outputs, layout [b][k][v], k = l*32 + j  (184.5 MB)
__device__ float g_feats[(size_t)NB * DFE * NV];

// ---------------- shared memory layout (kernel 1) ----------------
struct __align__(16) Smem1 {
    float hT[NF][NV];        // 32768 f : current h, transposed (thread-owned columns)
    float buf[NC][TPB1];     // 12288 f : per-chunk feat buffer (rows 0..19 f, 20..23 w)
    float warr[NA][NV];      // 4096  f : w for all vertices (out phase)
    float WoS[228][NF];      // 7296  f : staged W_out[l]
    float Wfs[NF][NC];       // 768   f : staged [Wf | Ws] (phase A: W_in[20][32]=640)
    float Gp[NA][NF];        // 128
    float aggmax[NA][NC];    // 96
    float aggsum[NA][NC];    // 96
    float bias_fw[NC];       // 24
    float bo[NF];            // 32
    float bnl_s[NF];         // 32
    float bnl_t[NF];         // 32
    float cbias[NF];         // 32
    float s0[20];            // 20
    float t0[20];            // 20
    float meanS[12];         // 12 (10 used)
    float part[16][12];      // 192
};
static_assert(sizeof(Smem1) <= 232448, "smem over 227KB limit");

__device__ __forceinline__ float fast_tanh(float x) {
    float ax = fabsf(x);
    float e  = __expf(ax + ax);
    float r  = __fdividef(2.0f, e + 1.0f);
    float t  = 1.0f - r;
    return copysignf(t, x);
}

// =====================================================================
// Kernel 1: GlobalExchange + input layer + 11 GarNet blocks
// grid = 128 (one CTA per event), 512 threads, ~226KB dynamic smem
// =====================================================================
__global__ __launch_bounds__(TPB1, 1)
void garnet_k1(const float* __restrict__ x,
               const float* __restrict__ bn0_gamma, const float* __restrict__ bn0_beta,
               const float* __restrict__ bn0_mean,  const float* __restrict__ bn0_var,
               const float* __restrict__ W_in,      const float* __restrict__ b_in,
               const float* __restrict__ W_flr,     const float* __restrict__ b_flr,
               const float* __restrict__ W_s,       const float* __restrict__ b_s,
               const float* __restrict__ W_out,     const float* __restrict__ b_out,
               const float* __restrict__ bn_gamma,  const float* __restrict__ bn_beta,
               const float* __restrict__ bn_mean,   const float* __restrict__ bn_var)
{
    extern __shared__ float smraw[];
    Smem1& S = *reinterpret_cast<Smem1*>(smraw);
    const int tid  = threadIdx.x;
    const int lane = tid & 31;
    const int warp = tid >> 5;
    const int b    = blockIdx.x;
    const float* xb = x + (size_t)b * NV * NFEAT;

    // ---------------- Phase A: mean over vertices ----------------
    {
        float s[NFEAT];
        #pragma unroll
        for (int c = 0; c < NFEAT; c++) s[c] = 0.0f;
        #pragma unroll
        for (int ch = 0; ch < 2; ch++) {
            const float* xv = xb + (size_t)(tid + ch * TPB1) * NFEAT;
            #pragma unroll
            for (int c = 0; c < NFEAT; c++) s[c] += xv[c];
        }
        #pragma unroll
        for (int o = 16; o > 0; o >>= 1) {
            #pragma unroll
            for (int c = 0; c < NFEAT; c++)
                s[c] += __shfl_xor_sync(0xffffffffu, s[c], o);
        }
        if (lane == 0) {
            #pragma unroll
            for (int c = 0; c < NFEAT; c++) S.part[warp][c] = s[c];
        }
    }
    // stage W_in into Wfs region; bn0 scale/shift
    float* WinS = &S.Wfs[0][0];                  // [20][32] = 640 floats
    for (int i = tid; i < 20 * NF; i += TPB1) WinS[i] = W_in[i];
    if (tid < 20) {
        float sc = bn0_gamma[tid] * rsqrtf(bn0_var[tid] + 1e-3f);
        S.s0[tid] = sc;
        S.t0[tid] = bn0_beta[tid] - bn0_mean[tid] * sc;
    }
    __syncthreads();
    if (tid < NFEAT) {
        float a = 0.0f;
        #pragma unroll
        for (int w = 0; w < 16; w++) a += S.part[w][tid];
        S.meanS[tid] = a * (1.0f / 1024.0f);
    }
    __syncthreads();
    if (tid < NF) {    // fold mean-half of gex + b_in into per-event constant bias
        float acc = b_in[tid];
        #pragma unroll
        for (int c = 10; c < 20; c++) {
            float g = S.meanS[c - 10] * S.s0[c] + S.t0[c];
            acc += g * WinS[c * NF + tid];
        }
        S.cbias[tid] = acc;
    }
    __syncthreads();

    // ---------------- Phase A: h0 = tanh(bn0(gex) @ W_in + b_in) ----------------
    #pragma unroll 1
    for (int ch = 0; ch < 2; ch++) {
        const int v = tid + ch * TPB1;
        const float* xv = xb + (size_t)v * NFEAT;
        float g[NFEAT];
        #pragma unroll
        for (int c = 0; c < NFEAT; c++) g[c] = xv[c] * S.s0[c] + S.t0[c];
        #pragma unroll
        for (int j4 = 0; j4 < 8; j4++) {
            float4 b4 = *reinterpret_cast<const float4*>(&S.cbias[j4 * 4]);
            float a0 = b4.x, a1 = b4.y, a2 = b4.z, a3 = b4.w;
            #pragma unroll
            for (int c = 0; c < NFEAT; c++) {
                float4 w4 = *reinterpret_cast<const float4*>(&WinS[c * NF + j4 * 4]);
                a0 += g[c] * w4.x; a1 += g[c] * w4.y; a2 += g[c] * w4.z; a3 += g[c] * w4.w;
            }
            S.hT[j4 * 4 + 0][v] = fast_tanh(a0);
            S.hT[j4 * 4 + 1][v] = fast_tanh(a1);
            S.hT[j4 * 4 + 2][v] = fast_tanh(a2);
            S.hT[j4 * 4 + 3][v] = fast_tanh(a3);
        }
    }

    // ---------------- GarNet blocks ----------------
    for (int l = 0; l < NBK; l++) {
        __syncthreads();   // guards: prev out-phase readers of WoS/Gp done; hT writes visible
        // stage weights
        {
            const float4* Wo4 = reinterpret_cast<const float4*>(W_out + (size_t)l * 228 * NF);
            float4* WoS4 = reinterpret_cast<float4*>(&S.WoS[0][0]);
            for (int i = tid; i < 228 * NF / 4; i += TPB1) WoS4[i] = Wo4[i];
        }
        for (int i = tid; i < NF * NC; i += TPB1) {
            int k = i / NC, c = i % NC;
            S.Wfs[k][c] = (c < NP) ? W_flr[((size_t)l * NF + k) * NP + c]
                                   : W_s[((size_t)l * NF + k) * NA + (c - NP)];
        }
        if (tid < NC) S.bias_fw[tid] = (tid < NP) ? b_flr[l * NP + tid] : b_s[l * NA + (tid - NP)];
        if (tid < NF) {
            S.bo[tid] = b_out[l * NF + tid];
            float sc = bn_gamma[l * NF + tid] * rsqrtf(bn_var[l * NF + tid] + 1e-3f);
            S.bnl_s[tid] = sc;
            S.bnl_t[tid] = bn_beta[l * NF + tid] - bn_mean[l * NF + tid] * sc;
        }
        __syncthreads();

        // per-warp reduction task accumulators (96 tasks = 16 warps x 6)
        float tmax[6], tsum[6];
        #pragma unroll
        for (int q = 0; q < 6; q++) { tmax[q] = -CUDART_INF_F; tsum[q] = 0.0f; }

        #pragma unroll 1
        for (int ch = 0; ch < 2; ch++) {
            const int v = tid + ch * TPB1;
            // f = h@Wf + bf ; d = h@Ws + bs ; w = exp(-|d|)
            {
                float h[NF];
                #pragma unroll
                for (int k = 0; k < NF; k++) h[k] = S.hT[k][v];
                #pragma unroll
                for (int c4 = 0; c4 < 6; c4++) {
                    float4 b4 = *reinterpret_cast<const float4*>(&S.bias_fw[c4 * 4]);
                    float a0 = b4.x, a1 = b4.y, a2 = b4.z, a3 = b4.w;
                    #pragma unroll
                    for (int k = 0; k < NF; k++) {
                        float4 w4 = *reinterpret_cast<const float4*>(&S.Wfs[k][c4 * 4]);
                        a0 += h[k] * w4.x; a1 += h[k] * w4.y; a2 += h[k] * w4.z; a3 += h[k] * w4.w;
                    }
                    if (c4 < 5) {
                        S.buf[c4 * 4 + 0][tid] = a0;
                        S.buf[c4 * 4 + 1][tid] = a1;
                        S.buf[c4 * 4 + 2][tid] = a2;
                        S.buf[c4 * 4 + 3][tid] = a3;
                    } else {
                        float w0 = __expf(-fabsf(a0)), w1 = __expf(-fabsf(a1));
                        float w2 = __expf(-fabsf(a2)), w3 = __expf(-fabsf(a3));
                        S.buf[20][tid] = w0; S.buf[21][tid] = w1;
                        S.buf[22][tid] = w2; S.buf[23][tid] = w3;
                        S.warr[0][v] = w0; S.warr[1][v] = w1;
                        S.warr[2][v] = w2; S.warr[3][v] = w3;
                    }
                }
            }
            __syncthreads();
            // scan: warp w owns tasks 6w..6w+5 ; task = a*24 + c
            {
                const int tbase = warp * 6;
                #pragma unroll
                for (int q = 0; q < 6; q++) {
                    const int task = tbase + q;
                    const int aa = task / NC, c = task % NC;
                    float m = tmax[q], sm = tsum[q];
                    #pragma unroll
                    for (int i = 0; i < TPB1 / 32; i++) {
                        int vv = lane + i * 32;
                        float val = S.buf[NP + aa][vv] * S.buf[c][vv];
                        m = fmaxf(m, val);
                        sm += val;
                    }
                    tmax[q] = m; tsum[q] = sm;
                }
            }
            __syncthreads();   // before next chunk overwrites buf
        }
        // finalize tasks across lanes
        #pragma unroll
        for (int q = 0; q < 6; q++) {
            float m = tmax[q], sm = tsum[q];
            #pragma unroll
            for (int o = 16; o > 0; o >>= 1) {
                m  = fmaxf(m, __shfl_xor_sync(0xffffffffu, m, o));
                sm += __shfl_xor_sync(0xffffffffu, sm, o);
            }
            if (lane == 0) {
                int task = warp * 6 + q;
                S.aggmax[task / NC][task % NC] = m;
                S.aggsum[task / NC][task % NC] = sm;
            }
        }
        __syncthreads();
        // Gp[a][j] = Wo[224+a][j] + sum_c2 agg[a][c2] * Wo[32+a*48+c2][j]
        if (tid < 128) {
            int aa = tid >> 5, j = tid & 31;
            float g = S.WoS[224 + aa][j];
            #pragma unroll
            for (int c2 = 0; c2 < NC; c2++)
                g += S.aggmax[aa][c2] * S.WoS[32 + aa * 48 + c2][j];
            #pragma unroll
            for (int c2 = 0; c2 < NC; c2++)
                g += (S.aggsum[aa][c2] * (1.0f / 1024.0f)) * S.WoS[32 + aa * 48 + NC + c2][j];
            S.Gp[aa][j] = g;
        }
        __syncthreads();

        // out phase: out[j] = bn(tanh(bo + h@Wo[0:32] + sum_a w_a * Gp[a]))
        float* fbase = g_feats + ((size_t)b * DFE + (size_t)l * NF) * NV;
        #pragma unroll 1
        for (int ch = 0; ch < 2; ch++) {
            const int v = tid + ch * TPB1;
            float h[NF];
            #pragma unroll
            for (int k = 0; k < NF; k++) h[k] = S.hT[k][v];
            float wl[NA];
            #pragma unroll
            for (int aa = 0; aa < NA; aa++) wl[aa] = S.warr[aa][v];
            #pragma unroll
            for (int j4 = 0; j4 < 8; j4++) {
                float4 b4 = *reinterpret_cast<const float4*>(&S.bo[j4 * 4]);
                float a0 = b4.x, a1 = b4.y, a2 = b4.z, a3 = b4.w;
                #pragma unroll
                for (int k = 0; k < NF; k++) {
                    float4 w4 = *reinterpret_cast<const float4*>(&S.WoS[k][j4 * 4]);
                    a0 += h[k] * w4.x; a1 += h[k] * w4.y; a2 += h[k] * w4.z; a3 += h[k] * w4.w;
                }
                #pragma unroll
                for (int aa = 0; aa < NA; aa++) {
                    float4 g4 = *reinterpret_cast<const float4*>(&S.Gp[aa][j4 * 4]);
                    float wa = wl[aa];
                    a0 += wa * g4.x; a1 += wa * g4.y; a2 += wa * g4.z; a3 += wa * g4.w;
                }
                const int j = j4 * 4;
                float o0 = fast_tanh(a0) * S.bnl_s[j + 0] + S.bnl_t[j + 0];
                float o1 = fast_tanh(a1) * S.bnl_s[j + 1] + S.bnl_t[j + 1];
                float o2 = fast_tanh(a2) * S.bnl_s[j + 2] + S.bnl_t[j + 2];
                float o3 = fast_tanh(a3) * S.bnl_s[j + 3] + S.bnl_t[j + 3];
                // thread-owned columns: no race
                S.hT[j + 0][v] = o0; S.hT[j + 1][v] = o1;
                S.hT[j + 2][v] = o2; S.hT[j + 3][v] = o3;
                fbase[(size_t)(j + 0) * NV + v] = o0;
                fbase[(size_t)(j + 1) * NV + v] = o1;
                fbase[(size_t)(j + 2) * NV + v] = o2;
                fbase[(size_t)(j + 3) * NV + v] = o3;
            }
        }
    }
}

// =====================================================================
// Kernel 2: out = relu(relu(feats @ W_o0 + b_o0) @ W_o1 + b_o1)
// grid = (128, 4), 256 threads; W_o0 staged in smem (~68KB)
// =====================================================================
#define K2_SMEMF (DFE * 48 + 144 + 48 + 4)

__global__ __launch_bounds__(K2_T, 2)
void garnet_k2(const float* __restrict__ W_o0, const float* __restrict__ b_o0,
               const float* __restrict__ W_o1, const float* __restrict__ b_o1,
               float* __restrict__ out)
{
    extern __shared__ float s2[];
    float* Ws  = s2;                 // [352][48]
    float* W1  = s2 + DFE * 48;      // [48][3]
    float* b0s = W1 + 144;
    float* b1s = b0s + 48;
    const int tid = threadIdx.x;
    {
        const float4* src = reinterpret_cast<const float4*>(W_o0);
        float4* dst = reinterpret_cast<float4*>(Ws);
        for (int i = tid; i < DFE * 48 / 4; i += K2_T) dst[i] = src[i];
    }
    if (tid < 144) W1[tid]  = W_o1[tid];
    if (tid < 48)  b0s[tid] = b_o0[tid];
    if (tid < 3)   b1s[tid] = b_o1[tid];
    __syncthreads();

    const int b = blockIdx.x;
    const int v = blockIdx.y * K2_T + tid;
    float hid[48];
    #pragma unroll
    for (int j = 0; j < 48; j++) hid[j] = b0s[j];

    const float* fp = g_feats + (size_t)b * DFE * NV + v;
    #pragma unroll 4
    for (int k = 0; k < DFE; k++) {
        float f = fp[(size_t)k * NV];
        #pragma unroll
        for (int j4 = 0; j4 < 12; j4++) {
            float4 w4 = *reinterpret_cast<const float4*>(&Ws[k * 48 + j4 * 4]);
            hid[j4 * 4 + 0] += f * w4.x;
            hid[j4 * 4 + 1] += f * w4.y;
            hid[j4 * 4 + 2] += f * w4.z;
            hid[j4 * 4 + 3] += f * w4.w;
        }
    }
    float o0 = b1s[0], o1 = b1s[1], o2 = b1s[2];
    #pragma unroll
    for (int j = 0; j < 48; j++) {
        float hj = fmaxf(hid[j], 0.0f);
        o0 += hj * W1[j * 3 + 0];
        o1 += hj * W1[j * 3 + 1];
        o2 += hj * W1[j * 3 + 2];
    }
    float* op = out + ((size_t)b * NV + v) * 3;
    op[0] = fmaxf(o0, 0.0f);
    op[1] = fmaxf(o1, 0.0f);
    op[2] = fmaxf(o2, 0.0f);
}

// =====================================================================
extern "C" void kernel_launch(void* const* d_in, const int* in_sizes, int n_in,
                              void* d_out, int out_size)
{
    const float* x         = (const float*)d_in[0];
    const float* bn0_gamma = (const float*)d_in[1];
    const float* bn0_beta  = (const float*)d_in[2];
    const float* bn0_mean  = (const float*)d_in[3];
    const float* bn0_var   = (const float*)d_in[4];
    const float* W_in      = (const float*)d_in[5];
    const float* b_in      = (const float*)d_in[6];
    const float* W_flr     = (const float*)d_in[7];
    const float* b_flr     = (const float*)d_in[8];
    const float* W_s       = (const float*)d_in[9];
    const float* b_s       = (const float*)d_in[10];
    const float* W_out     = (const float*)d_in[11];
    const float* b_out     = (const float*)d_in[12];
    const float* bn_gamma  = (const float*)d_in[13];
    const float* bn_beta   = (const float*)d_in[14];
    const float* bn_mean   = (const float*)d_in[15];
    const float* bn_var    = (const float*)d_in[16];
    const float* W_o0      = (const float*)d_in[17];
    const float* b_o0      = (const float*)d_in[18];
    const float* W_o1      = (const float*)d_in[19];
    const float* b_o1      = (const float*)d_in[20];

    cudaFuncSetAttribute(garnet_k1, cudaFuncAttributeMaxDynamicSharedMemorySize,
                         (int)sizeof(Smem1));
    cudaFuncSetAttribute(garnet_k2, cudaFuncAttributeMaxDynamicSharedMemorySize,
                         (int)(K2_SMEMF * sizeof(float)));

    garnet_k1<<<NB, TPB1, sizeof(Smem1)>>>(
        x, bn0_gamma, bn0_beta, bn0_mean, bn0_var, W_in, b_in,
        W_flr, b_flr, W_s, b_s, W_out, b_out,
        bn_gamma, bn_beta, bn_mean, bn_var);

    garnet_k2<<<dim3(NB, NV / K2_T), K2_T, K2_SMEMF * sizeof(float)>>>(
        W_o0, b_o0, W_o1, b_o1, (float*)d_out);
}

// round 4
// speedup vs baseline: 3.0945x; 3.0945x over previous
#include <cuda_runtime.h>
#include <math_constants.h>
#include <cstdint>
#include <cstddef>

// ---------------- problem constants ----------------
#define NB    128
#define NV    1024
#define NFEAT 10
#define NBK   11
#define NF    32
#define NP    20
#define NA    4
#define NC    24
#define DFE   352   // NBK*NF

// h ring: slot s in [0,12): slot 0 = h0, slot l+1 = output of block l.
// layout g_h[b][s*32 + k][v]  (v fastest -> coalesced)
__device__ float g_h[(size_t)NB * 384 * NV];     // 201 MB
__device__ float g_w[(size_t)NB * NA * NV];      // per-block edge weights
__device__ float g_pmax[NB * 96 * 4];            // per-quarter partial max
__device__ float g_psum[NB * 96 * 4];            // per-quarter partial sum
__device__ float g_cbias[NB * NF];               // per-event folded input bias

// ---------------- f32x2 packed-math helpers ----------------
__device__ __forceinline__ unsigned long long pk2(float a, float b) {
    unsigned long long r;
    asm("mov.b64 %0, {%1, %2};" : "=l"(r) : "f"(a), "f"(b));
    return r;
}
__device__ __forceinline__ unsigned long long dup2(float a) { return pk2(a, a); }
__device__ __forceinline__ void fma2(unsigned long long& d, unsigned long long a,
                                     unsigned long long b) {
    asm("fma.rn.f32x2 %0, %1, %2, %0;" : "+l"(d) : "l"(a), "l"(b));
}
__device__ __forceinline__ float2 up2(unsigned long long v) {
    float2 r;
    asm("mov.b64 {%0, %1}, %2;" : "=f"(r.x), "=f"(r.y) : "l"(v));
    return r;
}
union F4U { float4 f; unsigned long long u[2]; };

__device__ __forceinline__ float tanh_fast(float x) {
    float r;
    asm("tanh.approx.f32 %0, %1;" : "=f"(r) : "f"(x));
    return r;
}

// =====================================================================
// kA: per-event vertex mean + folded constant bias for the input layer
// grid 128, 256 threads
// =====================================================================
__global__ __launch_bounds__(256)
void kA(const float* __restrict__ x,
        const float* __restrict__ bn0_gamma, const float* __restrict__ bn0_beta,
        const float* __restrict__ bn0_mean,  const float* __restrict__ bn0_var,
        const float* __restrict__ W_in,      const float* __restrict__ b_in)
{
    __shared__ float sp[8][NFEAT];
    __shared__ float smean[NFEAT];
    __shared__ float ss0[20], st0[20];
    const int tid = threadIdx.x, b = blockIdx.x;
    const int lane = tid & 31, warp = tid >> 5;

    float s[NFEAT];
    #pragma unroll
    for (int c = 0; c < NFEAT; c++) s[c] = 0.0f;
    #pragma unroll
    for (int i = 0; i < 4; i++) {
        const float* xv = x + ((size_t)b * NV + tid + i * 256) * NFEAT;
        #pragma unroll
        for (int c = 0; c < NFEAT; c++) s[c] += xv[c];
    }
    #pragma unroll
    for (int o = 16; o > 0; o >>= 1)
        #pragma unroll
        for (int c = 0; c < NFEAT; c++) s[c] += __shfl_xor_sync(~0u, s[c], o);
    if (lane == 0)
        #pragma unroll
        for (int c = 0; c < NFEAT; c++) sp[warp][c] = s[c];
    if (tid < 20) {
        float sc = bn0_gamma[tid] * rsqrtf(bn0_var[tid] + 1e-3f);
        ss0[tid] = sc;
        st0[tid] = bn0_beta[tid] - bn0_mean[tid] * sc;
    }
    __syncthreads();
    if (tid < NFEAT) {
        float a = 0.0f;
        #pragma unroll
        for (int w = 0; w < 8; w++) a += sp[w][tid];
        smean[tid] = a * (1.0f / 1024.0f);
    }
    __syncthreads();
    if (tid < NF) {
        float a = b_in[tid];
        #pragma unroll
        for (int c = 10; c < 20; c++) {
            float g = smean[c - 10] * ss0[c] + st0[c];
            a += g * W_in[c * NF + tid];
        }
        g_cbias[b * NF + tid] = a;
    }
}

// =====================================================================
// kB: input layer  h0 = tanh(bn0(x) @ W_in[0:10] + cbias)  -> slot 0
// grid 512 (b = blk>>2, quarter = blk&3), 256 threads
// =====================================================================
__global__ __launch_bounds__(256)
void kB(const float* __restrict__ x,
        const float* __restrict__ bn0_gamma, const float* __restrict__ bn0_beta,
        const float* __restrict__ bn0_mean,  const float* __restrict__ bn0_var,
        const float* __restrict__ W_in)
{
    __shared__ float sW[NFEAT][NF];
    __shared__ float scb[NF];
    __shared__ float ss0[NFEAT], st0[NFEAT];
    const int tid = threadIdx.x;
    const int b = blockIdx.x >> 2, q = blockIdx.x & 3;
    const int v = q * 256 + tid;

    for (int i = tid; i < NFEAT * NF; i += 256) sW[i / NF][i % NF] = W_in[i];
    if (tid < NF) scb[tid] = g_cbias[b * NF + tid];
    if (tid < NFEAT) {
        float sc = bn0_gamma[tid] * rsqrtf(bn0_var[tid] + 1e-3f);
        ss0[tid] = sc;
        st0[tid] = bn0_beta[tid] - bn0_mean[tid] * sc;
    }
    __syncthreads();

    const float* xv = x + ((size_t)b * NV + v) * NFEAT;
    float g[NFEAT];
    #pragma unroll
    for (int c = 0; c < NFEAT; c++) g[c] = xv[c] * ss0[c] + st0[c];

    unsigned long long acc[16];
    #pragma unroll
    for (int j = 0; j < 16; j++) {
        float2 bb = *(const float2*)&scb[2 * j];
        acc[j] = pk2(bb.x, bb.y);
    }
    #pragma unroll
    for (int c = 0; c < NFEAT; c++) {
        unsigned long long gc = dup2(g[c]);
        #pragma unroll
        for (int g8 = 0; g8 < 8; g8++) {
            F4U w; w.f = *(const float4*)&sW[c][g8 * 4];
            fma2(acc[g8 * 2], gc, w.u[0]);
            fma2(acc[g8 * 2 + 1], gc, w.u[1]);
        }
    }
    float* ob = g_h + (size_t)b * 384 * NV + v;
    #pragma unroll
    for (int j2 = 0; j2 < 16; j2++) {
        float2 o = up2(acc[j2]);
        ob[(size_t)(2 * j2) * NV]     = tanh_fast(o.x);
        ob[(size_t)(2 * j2 + 1) * NV] = tanh_fast(o.y);
    }
}

// =====================================================================
// K_fw: block l -> f(20)/w(4) per vertex, w to global, partial max/sum
// grid 512 (b = blk>>2, quarter q = blk&3), 256 threads, 1 vertex/thread
// =====================================================================
__global__ __launch_bounds__(256)
void k_fw(int l,
          const float* __restrict__ W_flr, const float* __restrict__ b_flr,
          const float* __restrict__ W_s,   const float* __restrict__ b_s)
{
    __shared__ float sW[NF][NC];       // [32][24]
    __shared__ float sb[NC];
    __shared__ float sbuf[NC][256];
    const int tid = threadIdx.x;
    const int b = blockIdx.x >> 2, q = blockIdx.x & 3;
    const int v = q * 256 + tid;
    const int warp = tid >> 5, lane = tid & 31;

    for (int i = tid; i < NF * NC; i += 256) {
        int k = i / NC, c = i % NC;
        sW[k][c] = (c < NP) ? W_flr[((size_t)l * NF + k) * NP + c]
                            : W_s[((size_t)l * NF + k) * NA + (c - NP)];
    }
    if (tid < NC) sb[tid] = (tid < NP) ? b_flr[l * NP + tid] : b_s[l * NA + tid - NP];
    __syncthreads();

    const float* hb = g_h + ((size_t)b * 384 + (size_t)l * NF) * NV + v;
    float h[NF];
    #pragma unroll
    for (int k = 0; k < NF; k++) h[k] = hb[(size_t)k * NV];

    unsigned long long acc[12];
    #pragma unroll
    for (int j = 0; j < 12; j++) {
        float2 bb = *(const float2*)&sb[2 * j];
        acc[j] = pk2(bb.x, bb.y);
    }
    #pragma unroll
    for (int k = 0; k < NF; k++) {
        unsigned long long hk = dup2(h[k]);
        #pragma unroll
        for (int g6 = 0; g6 < 6; g6++) {
            F4U w; w.f = *(const float4*)&sW[k][g6 * 4];
            fma2(acc[g6 * 2], hk, w.u[0]);
            fma2(acc[g6 * 2 + 1], hk, w.u[1]);
        }
    }
    #pragma unroll
    for (int j = 0; j < 10; j++) {
        float2 o = up2(acc[j]);
        sbuf[2 * j][tid] = o.x;
        sbuf[2 * j + 1][tid] = o.y;
    }
    float wv[NA];
    {
        float2 o = up2(acc[10]);
        wv[0] = __expf(-fabsf(o.x)); wv[1] = __expf(-fabsf(o.y));
        float2 p = up2(acc[11]);
        wv[2] = __expf(-fabsf(p.x)); wv[3] = __expf(-fabsf(p.y));
    }
    #pragma unroll
    for (int a = 0; a < NA; a++) {
        sbuf[NP + a][tid] = wv[a];
        g_w[((size_t)b * NA + a) * NV + v] = wv[a];
    }
    __syncthreads();

    // 96 reduction tasks over this quarter's 256 vertices: 8 warps x 12 tasks
    #pragma unroll
    for (int qq = 0; qq < 12; qq++) {
        const int t = warp * 12 + qq;
        const int aa = t / NC, c = t % NC;
        float m = -CUDART_INF_F, s = 0.0f;
        #pragma unroll
        for (int i = 0; i < 8; i++) {
            float val = sbuf[NP + aa][lane + i * 32] * sbuf[c][lane + i * 32];
            m = fmaxf(m, val);
            s += val;
        }
        #pragma unroll
        for (int o = 16; o > 0; o >>= 1) {
            m = fmaxf(m, __shfl_xor_sync(~0u, m, o));
            s += __shfl_xor_sync(~0u, s, o);
        }
        if (lane == 0) {
            g_pmax[((size_t)b * 96 + t) * 4 + q] = m;
            g_psum[((size_t)b * 96 + t) * 4 + q] = s;
        }
    }
}

// =====================================================================
// K_out: combine partials -> Gp -> out = bn(tanh(h@Wo32 + sum_a w_a*Gp[a]))
// grid 512, 256 threads, 1 vertex/thread; writes slot l+1
// =====================================================================
__global__ __launch_bounds__(256)
void k_out(int l,
           const float* __restrict__ W_out,    const float* __restrict__ b_out,
           const float* __restrict__ bn_gamma, const float* __restrict__ bn_beta,
           const float* __restrict__ bn_mean,  const float* __restrict__ bn_var)
{
    __shared__ float sWo[228][NF];     // 29 KB
    __shared__ float sGp[NA][NF];
    __shared__ float sam[96], sas[96];
    __shared__ float sbo[NF], sscale[NF], sshift[NF];
    const int tid = threadIdx.x;
    const int b = blockIdx.x >> 2, q = blockIdx.x & 3;
    const int v = q * 256 + tid;

    {
        const float4* src = (const float4*)(W_out + (size_t)l * 228 * NF);
        float4* dst = (float4*)&sWo[0][0];
        for (int i = tid; i < 228 * NF / 4; i += 256) dst[i] = src[i];
    }
    if (tid < 96) {
        const float* pm = &g_pmax[((size_t)b * 96 + tid) * 4];
        const float* ps = &g_psum[((size_t)b * 96 + tid) * 4];
        sam[tid] = fmaxf(fmaxf(pm[0], pm[1]), fmaxf(pm[2], pm[3]));
        sas[tid] = (ps[0] + ps[1] + ps[2] + ps[3]) * (1.0f / 1024.0f);
    }
    if (tid >= 128 && tid < 160) {
        int j = tid - 128;
        sbo[j] = b_out[l * NF + j];
        float sc = bn_gamma[l * NF + j] * rsqrtf(bn_var[l * NF + j] + 1e-3f);
        sscale[j] = sc;
        sshift[j] = bn_beta[l * NF + j] - bn_mean[l * NF + j] * sc;
    }
    __syncthreads();
    if (tid < 128) {
        int aa = tid >> 5, j = tid & 31;
        float g = sWo[224 + aa][j];
        #pragma unroll
        for (int c = 0; c < NC; c++) g += sam[aa * NC + c] * sWo[32 + aa * 48 + c][j];
        #pragma unroll
        for (int c = 0; c < NC; c++) g += sas[aa * NC + c] * sWo[32 + aa * 48 + NC + c][j];
        sGp[aa][j] = g;
    }
    __syncthreads();

    const float* hb = g_h + ((size_t)b * 384 + (size_t)l * NF) * NV + v;
    float h[NF];
    #pragma unroll
    for (int k = 0; k < NF; k++) h[k] = hb[(size_t)k * NV];
    float wv[NA];
    #pragma unroll
    for (int a = 0; a < NA; a++) wv[a] = g_w[((size_t)b * NA + a) * NV + v];

    unsigned long long acc[16];
    #pragma unroll
    for (int j = 0; j < 16; j++) {
        float2 bb = *(const float2*)&sbo[2 * j];
        acc[j] = pk2(bb.x, bb.y);
    }
    #pragma unroll
    for (int k = 0; k < NF; k++) {
        unsigned long long hk = dup2(h[k]);
        #pragma unroll
        for (int g8 = 0; g8 < 8; g8++) {
            F4U w; w.f = *(const float4*)&sWo[k][g8 * 4];
            fma2(acc[g8 * 2], hk, w.u[0]);
            fma2(acc[g8 * 2 + 1], hk, w.u[1]);
        }
    }
    #pragma unroll
    for (int a = 0; a < NA; a++) {
        unsigned long long wa = dup2(wv[a]);
        #pragma unroll
        for (int g8 = 0; g8 < 8; g8++) {
            F4U gg; gg.f = *(const float4*)&sGp[a][g8 * 4];
            fma2(acc[g8 * 2], wa, gg.u[0]);
            fma2(acc[g8 * 2 + 1], wa, gg.u[1]);
        }
    }
    float* ob = g_h + ((size_t)b * 384 + (size_t)(l + 1) * NF) * NV + v;
    #pragma unroll
    for (int j2 = 0; j2 < 16; j2++) {
        float2 o = up2(acc[j2]);
        ob[(size_t)(2 * j2) * NV]     = tanh_fast(o.x) * sscale[2 * j2] + sshift[2 * j2];
        ob[(size_t)(2 * j2 + 1) * NV] = tanh_fast(o.y) * sscale[2 * j2 + 1] + sshift[2 * j2 + 1];
    }
}

// =====================================================================
// k2: out = relu(relu(feats @ W_o0 + b_o0) @ W_o1 + b_o1)
// feats = g_h slots 1..11. grid 256 (b = blk>>1, half = blk&1),
// 256 threads, 2 adjacent vertices/thread, packed f32x2, W_o0 in smem
// =====================================================================
#define K2_SMEMF (DFE * 48 + 144 + 48 + 4)

__global__ __launch_bounds__(256, 2)
void k2_mlp(const float* __restrict__ W_o0, const float* __restrict__ b_o0,
            const float* __restrict__ W_o1, const float* __restrict__ b_o1,
            float* __restrict__ out)
{
    extern __shared__ float s2[];
    float* Ws  = s2;
    float* sW1 = s2 + DFE * 48;
    float* sb0 = sW1 + 144;
    float* sb1 = sb0 + 48;
    const int tid = threadIdx.x;
    {
        const float4* src = (const float4*)W_o0;
        float4* dst = (float4*)Ws;
        for (int i = tid; i < DFE * 48 / 4; i += 256) dst[i] = src[i];
    }
    if (tid < 144) sW1[tid] = W_o1[tid];
    if (tid < 48)  sb0[tid] = b_o0[tid];
    if (tid < 3)   sb1[tid] = b_o1[tid];
    __syncthreads();

    const int b = blockIdx.x >> 1, half = blockIdx.x & 1;
    const int v0 = half * 512 + tid * 2;

    unsigned long long acc0[24], acc1[24];
    #pragma unroll
    for (int j = 0; j < 24; j++) {
        float2 bb = *(const float2*)&sb0[2 * j];
        unsigned long long p = pk2(bb.x, bb.y);
        acc0[j] = p; acc1[j] = p;
    }
    const float* fb = g_h + ((size_t)b * 384 + NF) * NV + v0;
    #pragma unroll 2
    for (int k = 0; k < DFE; k++) {
        float2 f = *(const float2*)(fb + (size_t)k * NV);
        unsigned long long f0 = dup2(f.x), f1 = dup2(f.y);
        #pragma unroll
        for (int g12 = 0; g12 < 12; g12++) {
            F4U w; w.f = *(const float4*)&Ws[k * 48 + g12 * 4];
            fma2(acc0[g12 * 2],     f0, w.u[0]);
            fma2(acc0[g12 * 2 + 1], f0, w.u[1]);
            fma2(acc1[g12 * 2],     f1, w.u[0]);
            fma2(acc1[g12 * 2 + 1], f1, w.u[1]);
        }
    }
    #pragma unroll
    for (int m = 0; m < 2; m++) {
        const unsigned long long* acc = m ? acc1 : acc0;
        float o0 = sb1[0], o1 = sb1[1], o2 = sb1[2];
        #pragma unroll
        for (int j2 = 0; j2 < 24; j2++) {
            float2 hv = up2(acc[j2]);
            float a = fmaxf(hv.x, 0.0f), c = fmaxf(hv.y, 0.0f);
            o0 += a * sW1[(2 * j2) * 3 + 0] + c * sW1[(2 * j2 + 1) * 3 + 0];
            o1 += a * sW1[(2 * j2) * 3 + 1] + c * sW1[(2 * j2 + 1) * 3 + 1];
            o2 += a * sW1[(2 * j2) * 3 + 2] + c * sW1[(2 * j2 + 1) * 3 + 2];
        }
        float* op = out + ((size_t)b * NV + v0 + m) * 3;
        op[0] = fmaxf(o0, 0.0f);
        op[1] = fmaxf(o1, 0.0f);
        op[2] = fmaxf(o2, 0.0f);
    }
}

// =====================================================================
extern "C" void kernel_launch(void* const* d_in, const int* in_sizes, int n_in,
                              void* d_out, int out_size)
{
    const float* x         = (const float*)d_in[0];
    const float* bn0_gamma = (const float*)d_in[1];
    const float* bn0_beta  = (const float*)d_in[2];
    const float* bn0_mean  = (const float*)d_in[3];
    const float* bn0_var   = (const float*)d_in[4];
    const float* W_in      = (const float*)d_in[5];
    const float* b_in      = (const float*)d_in[6];
    const float* W_flr     = (const float*)d_in[7];
    const float* b_flr     = (const float*)d_in[8];
    const float* W_s       = (const float*)d_in[9];
    const float* b_s       = (const float*)d_in[10];
    const float* W_out     = (const float*)d_in[11];
    const float* b_out     = (const float*)d_in[12];
    const float* bn_gamma  = (const float*)d_in[13];
    const float* bn_beta   = (const float*)d_in[14];
    const float* bn_mean   = (const float*)d_in[15];
    const float* bn_var    = (const float*)d_in[16];
    const float* W_o0      = (const float*)d_in[17];
    const float* b_o0      = (const float*)d_in[18];
    const float* W_o1      = (const float*)d_in[19];
    const float* b_o1      = (const float*)d_in[20];

    cudaFuncSetAttribute(k2_mlp, cudaFuncAttributeMaxDynamicSharedMemorySize,
                         (int)(K2_SMEMF * sizeof(float)));

    kA<<<NB, 256>>>(x, bn0_gamma, bn0_beta, bn0_mean, bn0_var, W_in, b_in);
    kB<<<NB * 4, 256>>>(x, bn0_gamma, bn0_beta, bn0_mean, bn0_var, W_in);

    for (int l = 0; l < NBK; l++) {
        k_fw<<<NB * 4, 256>>>(l, W_flr, b_flr, W_s, b_s);
        k_out<<<NB * 4, 256>>>(l, W_out, b_out, bn_gamma, bn_beta, bn_mean, bn_var);
    }

    k2_mlp<<<NB * 2, 256, K2_SMEMF * sizeof(float)>>>(
        W_o0, b_o0, W_o1, b_o1, (float*)d_out);
}

// round 5
// speedup vs baseline: 3.2650x; 1.0551x over previous
#include <cuda_runtime.h>
#include <math_constants.h>
#include <cstdint>
#include <cstddef>

// ---------------- problem constants ----------------
#define NB    128
#define NV    1024
#define NFEAT 10
#define NBK   11
#define NF    32
#define NP    20
#define NA    4
#define NC    24
#define DFE   352   // NBK*NF

// h ring: slot 0 = h0, slot l+1 = output of block l. layout g_h[b][s*32+k][v]
__device__ float g_h[(size_t)NB * 384 * NV];     // 201 MB
__device__ float g_w[(size_t)NB * NA * NV];      // per-block edge weights
__device__ float g_pmax[2][NB * 96 * 4];         // double-buffered partial max
__device__ float g_psum[2][NB * 96 * 4];         // double-buffered partial sum
__device__ float g_cbias[NB * NF];               // per-event folded input bias

// ---------------- f32x2 packed-math helpers ----------------
__device__ __forceinline__ unsigned long long pk2(float a, float b) {
    unsigned long long r;
    asm("mov.b64 %0, {%1, %2};" : "=l"(r) : "f"(a), "f"(b));
    return r;
}
__device__ __forceinline__ unsigned long long dup2(float a) { return pk2(a, a); }
__device__ __forceinline__ void fma2(unsigned long long& d, unsigned long long a,
                                     unsigned long long b) {
    asm("fma.rn.f32x2 %0, %1, %2, %0;" : "+l"(d) : "l"(a), "l"(b));
}
__device__ __forceinline__ float2 up2(unsigned long long v) {
    float2 r;
    asm("mov.b64 {%0, %1}, %2;" : "=f"(r.x), "=f"(r.y) : "l"(v));
    return r;
}
union F4U { float4 f; unsigned long long u[2]; };

__device__ __forceinline__ float tanh_fast(float x) {
    float r;
    asm("tanh.approx.f32 %0, %1;" : "=f"(r) : "f"(x));
    return r;
}

// ---------------- shared device helpers ----------------
// streaming epilogue: acc (pre-tanh, 16 f32x2) -> tanh[/BN] -> write h slot ->
// immediately accumulate fw-GEMM (h_{next} @ [Wf|Ws]) into facc. No o[] array.
template<bool BN>
__device__ __forceinline__ void stream_epi_fw(
    unsigned long long acc[16],
    const float* __restrict__ sscale, const float* __restrict__ sshift,
    const float (*__restrict__ sWfw)[NC], const float* __restrict__ sbfw,
    float* __restrict__ ob, unsigned long long facc[12])
{
    #pragma unroll
    for (int j = 0; j < 12; j++) {
        float2 bb = *(const float2*)&sbfw[2 * j];
        facc[j] = pk2(bb.x, bb.y);
    }
    #pragma unroll
    for (int j2 = 0; j2 < 16; j2++) {
        float2 z = up2(acc[j2]);
        float o0 = tanh_fast(z.x), o1 = tanh_fast(z.y);
        if (BN) {
            o0 = o0 * sscale[2 * j2] + sshift[2 * j2];
            o1 = o1 * sscale[2 * j2 + 1] + sshift[2 * j2 + 1];
        }
        ob[(size_t)(2 * j2) * NV]     = o0;
        ob[(size_t)(2 * j2 + 1) * NV] = o1;
        unsigned long long d0 = dup2(o0), d1 = dup2(o1);
        #pragma unroll
        for (int g6 = 0; g6 < 6; g6++) {
            F4U w0; w0.f = *(const float4*)&sWfw[2 * j2][g6 * 4];
            F4U w1; w1.f = *(const float4*)&sWfw[2 * j2 + 1][g6 * 4];
            fma2(facc[2 * g6],     d0, w0.u[0]);
            fma2(facc[2 * g6 + 1], d0, w0.u[1]);
            fma2(facc[2 * g6],     d1, w1.u[0]);
            fma2(facc[2 * g6 + 1], d1, w1.u[1]);
        }
    }
}

// f/w into sbuf + w to global
__device__ __forceinline__ void fw_finish(
    unsigned long long facc[12], float (*__restrict__ sbuf)[256], int tid,
    float* __restrict__ gw)
{
    #pragma unroll
    for (int j = 0; j < 10; j++) {
        float2 f = up2(facc[j]);
        sbuf[2 * j][tid] = f.x;
        sbuf[2 * j + 1][tid] = f.y;
    }
    float2 a = up2(facc[10]), b2 = up2(facc[11]);
    float w0 = __expf(-fabsf(a.x)),  w1 = __expf(-fabsf(a.y));
    float w2 = __expf(-fabsf(b2.x)), w3 = __expf(-fabsf(b2.y));
    sbuf[20][tid] = w0; sbuf[21][tid] = w1;
    sbuf[22][tid] = w2; sbuf[23][tid] = w3;
    gw[0]          = w0; gw[(size_t)NV]     = w1;
    gw[(size_t)2 * NV] = w2; gw[(size_t)3 * NV] = w3;
}

// 96 max/sum reduction tasks over this quarter's 256 vertices -> partials[pb]
__device__ __forceinline__ void reduce96(
    const float (*__restrict__ sbuf)[256], int b, int q, int warp, int lane, int pb)
{
    #pragma unroll
    for (int qq = 0; qq < 12; qq++) {
        const int t = warp * 12 + qq;
        const int aa = t / NC, c = t % NC;
        float m = -CUDART_INF_F, s = 0.0f;
        #pragma unroll
        for (int i = 0; i < 8; i++) {
            float val = sbuf[NP + aa][lane + i * 32] * sbuf[c][lane + i * 32];
            m = fmaxf(m, val);
            s += val;
        }
        #pragma unroll
        for (int o = 16; o > 0; o >>= 1) {
            m = fmaxf(m, __shfl_xor_sync(~0u, m, o));
            s += __shfl_xor_sync(~0u, s, o);
        }
        if (lane == 0) {
            g_pmax[pb][((size_t)b * 96 + t) * 4 + q] = m;
            g_psum[pb][((size_t)b * 96 + t) * 4 + q] = s;
        }
    }
}

// =====================================================================
// kA: per-event vertex mean + folded constant bias for the input layer
// =====================================================================
__global__ __launch_bounds__(256)
void kA(const float* __restrict__ x,
        const float* __restrict__ bn0_gamma, const float* __restrict__ bn0_beta,
        const float* __restrict__ bn0_mean,  const float* __restrict__ bn0_var,
        const float* __restrict__ W_in,      const float* __restrict__ b_in)
{
    __shared__ float sp[8][NFEAT];
    __shared__ float smean[NFEAT];
    __shared__ float ss0[20], st0[20];
    const int tid = threadIdx.x, b = blockIdx.x;
    const int lane = tid & 31, warp = tid >> 5;

    float s[NFEAT];
    #pragma unroll
    for (int c = 0; c < NFEAT; c++) s[c] = 0.0f;
    #pragma unroll
    for (int i = 0; i < 4; i++) {
        const float* xv = x + ((size_t)b * NV + tid + i * 256) * NFEAT;
        #pragma unroll
        for (int c = 0; c < NFEAT; c++) s[c] += xv[c];
    }
    #pragma unroll
    for (int o = 16; o > 0; o >>= 1)
        #pragma unroll
        for (int c = 0; c < NFEAT; c++) s[c] += __shfl_xor_sync(~0u, s[c], o);
    if (lane == 0)
        #pragma unroll
        for (int c = 0; c < NFEAT; c++) sp[warp][c] = s[c];
    if (tid < 20) {
        float sc = bn0_gamma[tid] * rsqrtf(bn0_var[tid] + 1e-3f);
        ss0[tid] = sc;
        st0[tid] = bn0_beta[tid] - bn0_mean[tid] * sc;
    }
    __syncthreads();
    if (tid < NFEAT) {
        float a = 0.0f;
        #pragma unroll
        for (int w = 0; w < 8; w++) a += sp[w][tid];
        smean[tid] = a * (1.0f / 1024.0f);
    }
    __syncthreads();
    if (tid < NF) {
        float a = b_in[tid];
        #pragma unroll
        for (int c = 10; c < 20; c++) {
            float g = smean[c - 10] * ss0[c] + st0[c];
            a += g * W_in[c * NF + tid];
        }
        g_cbias[b * NF + tid] = a;
    }
}

// =====================================================================
// kB_fw: h0 = tanh(bn0(x)@W_in + cbias) -> slot 0, fused with fw(block 0)
// grid 512 (b=blk>>2, q=blk&3), 256 threads
// =====================================================================
__global__ __launch_bounds__(256, 3)
void kB_fw(const float* __restrict__ x,
           const float* __restrict__ bn0_gamma, const float* __restrict__ bn0_var,
           const float* __restrict__ bn0_beta,  const float* __restrict__ bn0_mean,
           const float* __restrict__ W_in,
           const float* __restrict__ W_flr, const float* __restrict__ b_flr,
           const float* __restrict__ W_s,   const float* __restrict__ b_s)
{
    __shared__ float sW[NFEAT][NF];
    __shared__ float scb[NF];
    __shared__ float ss0[NFEAT], st0[NFEAT];
    __shared__ float sWfw[NF][NC];
    __shared__ float sbfw[NC];
    __shared__ float sbuf[NC][256];
    const int tid = threadIdx.x;
    const int b = blockIdx.x >> 2, q = blockIdx.x & 3;
    const int v = q * 256 + tid;
    const int warp = tid >> 5, lane = tid & 31;

    const float* xv = x + ((size_t)b * NV + v) * NFEAT;
    float xr[NFEAT];
    #pragma unroll
    for (int c = 0; c < NFEAT; c++) xr[c] = xv[c];

    for (int i = tid; i < NFEAT * NF; i += 256) sW[i / NF][i % NF] = W_in[i];
    for (int i = tid; i < NF * NC; i += 256) {
        int k = i / NC, c = i % NC;
        sWfw[k][c] = (c < NP) ? W_flr[(size_t)k * NP + c] : W_s[(size_t)k * NA + (c - NP)];
    }
    if (tid < NF) scb[tid] = g_cbias[b * NF + tid];
    if (tid < NFEAT) {
        float sc = bn0_gamma[tid] * rsqrtf(bn0_var[tid] + 1e-3f);
        ss0[tid] = sc;
        st0[tid] = bn0_beta[tid] - bn0_mean[tid] * sc;
    }
    if (tid >= 64 && tid < 64 + NC)
        sbfw[tid - 64] = (tid - 64 < NP) ? b_flr[tid - 64] : b_s[tid - 64 - NP];
    __syncthreads();

    float g[NFEAT];
    #pragma unroll
    for (int c = 0; c < NFEAT; c++) g[c] = xr[c] * ss0[c] + st0[c];

    unsigned long long acc[16];
    #pragma unroll
    for (int j = 0; j < 16; j++) {
        float2 bb = *(const float2*)&scb[2 * j];
        acc[j] = pk2(bb.x, bb.y);
    }
    #pragma unroll
    for (int c = 0; c < NFEAT; c++) {
        unsigned long long gc = dup2(g[c]);
        #pragma unroll
        for (int g8 = 0; g8 < 8; g8++) {
            F4U w; w.f = *(const float4*)&sW[c][g8 * 4];
            fma2(acc[g8 * 2],     gc, w.u[0]);
            fma2(acc[g8 * 2 + 1], gc, w.u[1]);
        }
    }
    float* ob = g_h + (size_t)b * 384 * NV + v;
    unsigned long long facc[12];
    stream_epi_fw<false>(acc, nullptr, nullptr, sWfw, sbfw, ob, facc);
    fw_finish(facc, sbuf, tid, g_w + ((size_t)b * NA) * NV + v);
    __syncthreads();
    reduce96(sbuf, b, q, warp, lane, 0);
}

// =====================================================================
// F: fused block: Gp(l) -> out(l) -> h_{l+1} -> fw(l+1) -> partials(l+1)
// grid 512 (b=blk>>2, q=blk&3), 256 threads
// =====================================================================
__global__ __launch_bounds__(256, 3)
void F_block(int l,
             const float* __restrict__ W_out,    const float* __restrict__ b_out,
             const float* __restrict__ bn_gamma, const float* __restrict__ bn_beta,
             const float* __restrict__ bn_mean,  const float* __restrict__ bn_var,
             const float* __restrict__ W_flr,    const float* __restrict__ b_flr,
             const float* __restrict__ W_s,      const float* __restrict__ b_s)
{
    __shared__ float sWo32[NF][NF];    // rows 0..31 of W_out[l]
    __shared__ float sWfw[NF][NC];     // fw weights of block l+1
    __shared__ float sGp[NA][NF];
    __shared__ float sam[96], sas[96];
    __shared__ float sbfw[NC];
    __shared__ float sbo[NF], sscale[NF], sshift[NF];
    __shared__ float sbuf[NC][256];
    const int tid = threadIdx.x;
    const int b = blockIdx.x >> 2, q = blockIdx.x & 3;
    const int v = q * 256 + tid;
    const int warp = tid >> 5, lane = tid & 31;
    const int pb = l & 1;
    const int lf = l + 1;

    // issue long-latency per-vertex loads first
    const float* hb = g_h + ((size_t)b * 384 + (size_t)l * NF) * NV + v;
    float wv[NA];
    #pragma unroll
    for (int a = 0; a < NA; a++) wv[a] = g_w[((size_t)b * NA + a) * NV + v];
    float h[16];
    #pragma unroll
    for (int k = 0; k < 16; k++) h[k] = hb[(size_t)k * NV];

    // stage
    const float* WoG = W_out + (size_t)l * 228 * NF;
    {
        const float4* src = (const float4*)WoG;
        float4* dst = (float4*)&sWo32[0][0];
        for (int i = tid; i < NF * NF / 4; i += 256) dst[i] = src[i];
    }
    for (int i = tid; i < NF * NC; i += 256) {
        int k = i / NC, c = i % NC;
        sWfw[k][c] = (c < NP) ? W_flr[((size_t)lf * NF + k) * NP + c]
                              : W_s[((size_t)lf * NF + k) * NA + (c - NP)];
    }
    if (tid < 96) {
        const float* pm = &g_pmax[pb][((size_t)b * 96 + tid) * 4];
        const float* ps = &g_psum[pb][((size_t)b * 96 + tid) * 4];
        sam[tid] = fmaxf(fmaxf(pm[0], pm[1]), fmaxf(pm[2], pm[3]));
        sas[tid] = (ps[0] + ps[1] + ps[2] + ps[3]) * (1.0f / 1024.0f);
    }
    if (tid >= 128 && tid < 160) {
        int j = tid - 128;
        sbo[j] = b_out[l * NF + j];
        float sc = bn_gamma[l * NF + j] * rsqrtf(bn_var[l * NF + j] + 1e-3f);
        sscale[j] = sc;
        sshift[j] = bn_beta[l * NF + j] - bn_mean[l * NF + j] * sc;
    }
    if (tid >= 160 && tid < 160 + NC)
        sbfw[tid - 160] = (tid - 160 < NP) ? b_flr[lf * NP + tid - 160]
                                           : b_s[lf * NA + tid - 160 - NP];
    __syncthreads();

    // Gp from global W_out rows (L2-hot, coalesced per warp)
    if (tid < 128) {
        const int aa = warp, j = lane;
        float g = WoG[(224 + aa) * NF + j];
        #pragma unroll
        for (int c = 0; c < NC; c++)
            g += sam[aa * NC + c] * WoG[(32 + aa * 48 + c) * NF + j];
        #pragma unroll
        for (int c = 0; c < NC; c++)
            g += sas[aa * NC + c] * WoG[(32 + aa * 48 + NC + c) * NF + j];
        sGp[aa][j] = g;
    }
    __syncthreads();

    // out-GEMM: acc = bo + h@Wo32 + sum_a w_a*Gp[a]
    unsigned long long acc[16];
    #pragma unroll
    for (int j = 0; j < 16; j++) {
        float2 bb = *(const float2*)&sbo[2 * j];
        acc[j] = pk2(bb.x, bb.y);
    }
    #pragma unroll
    for (int k = 0; k < 16; k++) {
        unsigned long long hk = dup2(h[k]);
        #pragma unroll
        for (int g8 = 0; g8 < 8; g8++) {
            F4U w; w.f = *(const float4*)&sWo32[k][g8 * 4];
            fma2(acc[g8 * 2],     hk, w.u[0]);
            fma2(acc[g8 * 2 + 1], hk, w.u[1]);
        }
    }
    #pragma unroll
    for (int k = 0; k < 16; k++) h[k] = hb[(size_t)(16 + k) * NV];
    #pragma unroll
    for (int k = 0; k < 16; k++) {
        unsigned long long hk = dup2(h[k]);
        #pragma unroll
        for (int g8 = 0; g8 < 8; g8++) {
            F4U w; w.f = *(const float4*)&sWo32[16 + k][g8 * 4];
            fma2(acc[g8 * 2],     hk, w.u[0]);
            fma2(acc[g8 * 2 + 1], hk, w.u[1]);
        }
    }
    #pragma unroll
    for (int a = 0; a < NA; a++) {
        unsigned long long wa = dup2(wv[a]);
        #pragma unroll
        for (int g8 = 0; g8 < 8; g8++) {
            F4U gg; gg.f = *(const float4*)&sGp[a][g8 * 4];
            fma2(acc[g8 * 2],     wa, gg.u[0]);
            fma2(acc[g8 * 2 + 1], wa, gg.u[1]);
        }
    }

    // streaming epilogue: tanh/BN -> write slot l+1 -> fused fw(l+1)
    float* ob = g_h + ((size_t)b * 384 + (size_t)lf * NF) * NV + v;
    unsigned long long facc[12];
    stream_epi_fw<true>(acc, sscale, sshift, sWfw, sbfw, ob, facc);
    fw_finish(facc, sbuf, tid, g_w + ((size_t)b * NA) * NV + v);
    __syncthreads();
    reduce96(sbuf, b, q, warp, lane, pb ^ 1);
}

// =====================================================================
// G: final block (l=10): out only, no fw. writes slot 11
// =====================================================================
__global__ __launch_bounds__(256, 3)
void G_block(const float* __restrict__ W_out,    const float* __restrict__ b_out,
             const float* __restrict__ bn_gamma, const float* __restrict__ bn_beta,
             const float* __restrict__ bn_mean,  const float* __restrict__ bn_var)
{
    __shared__ float sWo32[NF][NF];
    __shared__ float sGp[NA][NF];
    __shared__ float sam[96], sas[96];
    __shared__ float sbo[NF], sscale[NF], sshift[NF];
    const int tid = threadIdx.x;
    const int b = blockIdx.x >> 2, q = blockIdx.x & 3;
    const int v = q * 256 + tid;
    const int warp = tid >> 5, lane = tid & 31;
    const int l = 10, pb = 0;

    const float* hb = g_h + ((size_t)b * 384 + (size_t)l * NF) * NV + v;
    float wv[NA];
    #pragma unroll
    for (int a = 0; a < NA; a++) wv[a] = g_w[((size_t)b * NA + a) * NV + v];
    float h[16];
    #pragma unroll
    for (int k = 0; k < 16; k++) h[k] = hb[(size_t)k * NV];

    const float* WoG = W_out + (size_t)l * 228 * NF;
    {
        const float4* src = (const float4*)WoG;
        float4* dst = (float4*)&sWo32[0][0];
        for (int i = tid; i < NF * NF / 4; i += 256) dst[i] = src[i];
    }
    if (tid < 96) {
        const float* pm = &g_pmax[pb][((size_t)b * 96 + tid) * 4];
        const float* ps = &g_psum[pb][((size_t)b * 96 + tid) * 4];
        sam[tid] = fmaxf(fmaxf(pm[0], pm[1]), fmaxf(pm[2], pm[3]));
        sas[tid] = (ps[0] + ps[1] + ps[2] + ps[3]) * (1.0f / 1024.0f);
    }
    if (tid >= 128 && tid < 160) {
        int j = tid - 128;
        sbo[j] = b_out[l * NF + j];
        float sc = bn_gamma[l * NF + j] * rsqrtf(bn_var[l * NF + j] + 1e-3f);
        sscale[j] = sc;
        sshift[j] = bn_beta[l * NF + j] - bn_mean[l * NF + j] * sc;
    }
    __syncthreads();
    if (tid < 128) {
        const int aa = warp, j = lane;
        float g = WoG[(224 + aa) * NF + j];
        #pragma unroll
        for (int c = 0; c < NC; c++)
            g += sam[aa * NC + c] * WoG[(32 + aa * 48 + c) * NF + j];
        #pragma unroll
        for (int c = 0; c < NC; c++)
            g += sas[aa * NC + c] * WoG[(32 + aa * 48 + NC + c) * NF + j];
        sGp[aa][j] = g;
    }
    __syncthreads();

    unsigned long long acc[16];
    #pragma unroll
    for (int j = 0; j < 16; j++) {
        float2 bb = *(const float2*)&sbo[2 * j];
        acc[j] = pk2(bb.x, bb.y);
    }
    #pragma unroll
    for (int k = 0; k < 16; k++) {
        unsigned long long hk = dup2(h[k]);
        #pragma unroll
        for (int g8 = 0; g8 < 8; g8++) {
            F4U w; w.f = *(const float4*)&sWo32[k][g8 * 4];
            fma2(acc[g8 * 2],     hk, w.u[0]);
            fma2(acc[g8 * 2 + 1], hk, w.u[1]);
        }
    }
    #pragma unroll
    for (int k = 0; k < 16; k++) h[k] = hb[(size_t)(16 + k) * NV];
    #pragma unroll
    for (int k = 0; k < 16; k++) {
        unsigned long long hk = dup2(h[k]);
        #pragma unroll
        for (int g8 = 0; g8 < 8; g8++) {
            F4U w; w.f = *(const float4*)&sWo32[16 + k][g8 * 4];
            fma2(acc[g8 * 2],     hk, w.u[0]);
            fma2(acc[g8 * 2 + 1], hk, w.u[1]);
        }
    }
    #pragma unroll
    for (int a = 0; a < NA; a++) {
        unsigned long long wa = dup2(wv[a]);
        #pragma unroll
        for (int g8 = 0; g8 < 8; g8++) {
            F4U gg; gg.f = *(const float4*)&sGp[a][g8 * 4];
            fma2(acc[g8 * 2],     wa, gg.u[0]);
            fma2(acc[g8 * 2 + 1], wa, gg.u[1]);
        }
    }
    float* ob = g_h + ((size_t)b * 384 + (size_t)11 * NF) * NV + v;
    #pragma unroll
    for (int j2 = 0; j2 < 16; j2++) {
        float2 z = up2(acc[j2]);
        ob[(size_t)(2 * j2) * NV]     = tanh_fast(z.x) * sscale[2 * j2] + sshift[2 * j2];
        ob[(size_t)(2 * j2 + 1) * NV] = tanh_fast(z.y) * sscale[2 * j2 + 1] + sshift[2 * j2 + 1];
    }
}

// =====================================================================
// k2: out = relu(relu(feats @ W_o0 + b_o0) @ W_o1 + b_o1); feats = slots 1..11
// =====================================================================
#define K2_SMEMF (DFE * 48 + 144 + 48 + 4)

__global__ __launch_bounds__(256, 2)
void k2_mlp(const float* __restrict__ W_o0, const float* __restrict__ b_o0,
            const float* __restrict__ W_o1, const float* __restrict__ b_o1,
            float* __restrict__ out)
{
    extern __shared__ float s2[];
    float* Ws  = s2;
    float* sW1 = s2 + DFE * 48;
    float* sb0 = sW1 + 144;
    float* sb1 = sb0 + 48;
    const int tid = threadIdx.x;
    {
        const float4* src = (const float4*)W_o0;
        float4* dst = (float4*)Ws;
        for (int i = tid; i < DFE * 48 / 4; i += 256) dst[i] = src[i];
    }
    if (tid < 144) sW1[tid] = W_o1[tid];
    if (tid < 48)  sb0[tid] = b_o0[tid];
    if (tid < 3)   sb1[tid] = b_o1[tid];
    __syncthreads();

    const int b = blockIdx.x >> 1, half = blockIdx.x & 1;
    const int v0 = half * 512 + tid * 2;

    unsigned long long acc0[24], acc1[24];
    #pragma unroll
    for (int j = 0; j < 24; j++) {
        float2 bb = *(const float2*)&sb0[2 * j];
        unsigned long long p = pk2(bb.x, bb.y);
        acc0[j] = p; acc1[j] = p;
    }
    const float* fb = g_h + ((size_t)b * 384 + NF) * NV + v0;
    #pragma unroll 4
    for (int k = 0; k < DFE; k++) {
        float2 f = *(const float2*)(fb + (size_t)k * NV);
        unsigned long long f0 = dup2(f.x), f1 = dup2(f.y);
        #pragma unroll
        for (int g12 = 0; g12 < 12; g12++) {
            F4U w; w.f = *(const float4*)&Ws[k * 48 + g12 * 4];
            fma2(acc0[g12 * 2],     f0, w.u[0]);
            fma2(acc0[g12 * 2 + 1], f0, w.u[1]);
            fma2(acc1[g12 * 2],     f1, w.u[0]);
            fma2(acc1[g12 * 2 + 1], f1, w.u[1]);
        }
    }
    #pragma unroll
    for (int m = 0; m < 2; m++) {
        const unsigned long long* acc = m ? acc1 : acc0;
        float o0 = sb1[0], o1 = sb1[1], o2 = sb1[2];
        #pragma unroll
        for (int j2 = 0; j2 < 24; j2++) {
            float2 hv = up2(acc[j2]);
            float a = fmaxf(hv.x, 0.0f), c = fmaxf(hv.y, 0.0f);
            o0 += a * sW1[(2 * j2) * 3 + 0] + c * sW1[(2 * j2 + 1) * 3 + 0];
            o1 += a * sW1[(2 * j2) * 3 + 1] + c * sW1[(2 * j2 + 1) * 3 + 1];
            o2 += a * sW1[(2 * j2) * 3 + 2] + c * sW1[(2 * j2 + 1) * 3 + 2];
        }
        float* op = out + ((size_t)b * NV + v0 + m) * 3;
        op[0] = fmaxf(o0, 0.0f);
        op[1] = fmaxf(o1, 0.0f);
        op[2] = fmaxf(o2, 0.0f);
    }
}

// =====================================================================
extern "C" void kernel_launch(void* const* d_in, const int* in_sizes, int n_in,
                              void* d_out, int out_size)
{
    const float* x         = (const float*)d_in[0];
    const float* bn0_gamma = (const float*)d_in[1];
    const float* bn0_beta  = (const float*)d_in[2];
    const float* bn0_mean  = (const float*)d_in[3];
    const float* bn0_var   = (const float*)d_in[4];
    const float* W_in      = (const float*)d_in[5];
    const float* b_in      = (const float*)d_in[6];
    const float* W_flr     = (const float*)d_in[7];
    const float* b_flr     = (const float*)d_in[8];
    const float* W_s       = (const float*)d_in[9];
    const float* b_s       = (const float*)d_in[10];
    const float* W_out     = (const float*)d_in[11];
    const float* b_out     = (const float*)d_in[12];
    const float* bn_gamma  = (const float*)d_in[13];
    const float* bn_beta   = (const float*)d_in[14];
    const float* bn_mean   = (const float*)d_in[15];
    const float* bn_var    = (const float*)d_in[16];
    const float* W_o0      = (const float*)d_in[17];
    const float* b_o0      = (const float*)d_in[18];
    const float* W_o1      = (const float*)d_in[19];
    const float* b_o1      = (const float*)d_in[20];

    cudaFuncSetAttribute(k2_mlp, cudaFuncAttributeMaxDynamicSharedMemorySize,
                         (int)(K2_SMEMF * sizeof(float)));

    kA<<<NB, 256>>>(x, bn0_gamma, bn0_beta, bn0_mean, bn0_var, W_in, b_in);
    kB_fw<<<NB * 4, 256>>>(x, bn0_gamma, bn0_var, bn0_beta, bn0_mean, W_in,
                           W_flr, b_flr, W_s, b_s);

    for (int l = 0; l < NBK - 1; l++) {
        F_block<<<NB * 4, 256>>>(l, W_out, b_out, bn_gamma, bn_beta, bn_mean, bn_var,
                                 W_flr, b_flr, W_s, b_s);
    }
    G_block<<<NB * 4, 256>>>(W_out, b_out, bn_gamma, bn_beta, bn_mean, bn_var);

    k2_mlp<<<NB * 2, 256, K2_SMEMF * sizeof(float)>>>(
        W_o0, b_o0, W_o1, b_o1, (float*)d_out);
}

// round 7
// speedup vs baseline: 4.2702x; 1.3079x over previous
#include <cuda_runtime.h>
#include <math_constants.h>
#include <cstdint>
#include <cstddef>

// ---------------- problem constants ----------------
#define NB    128
#define NV    1024
#define NFEAT 10
#define NBK   11
#define NF    32
#define NP    20
#define NA    4
#define NC    24
#define DFE   352   // NBK*NF
#define HALF_V 512

// h ring: slot 0 = h0, slot l+1 = output of block l. layout g_h[b][s*32+k][v]
__device__ float g_h[(size_t)NB * 384 * NV];     // 201 MB
__device__ float g_w[(size_t)NB * NA * NV];      // per-block edge weights
__device__ float g_pmax[2][NB * 96 * 2];         // double-buffered partial max
__device__ float g_psum[2][NB * 96 * 2];         // double-buffered partial sum
__device__ float g_cbias[NB * NF];               // per-event folded input bias

// ---------------- f32x2 packed-math helpers ----------------
typedef unsigned long long ull;
__device__ __forceinline__ ull pk2(float a, float b) {
    ull r; asm("mov.b64 %0, {%1, %2};" : "=l"(r) : "f"(a), "f"(b)); return r;
}
__device__ __forceinline__ ull dup2(float a) { return pk2(a, a); }
__device__ __forceinline__ void fma2(ull& d, ull a, ull b) {
    asm("fma.rn.f32x2 %0, %1, %2, %0;" : "+l"(d) : "l"(a), "l"(b));
}
__device__ __forceinline__ ull mul2(ull a, ull b) {
    ull r; asm("mul.rn.f32x2 %0, %1, %2;" : "=l"(r) : "l"(a), "l"(b)); return r;
}
__device__ __forceinline__ ull add2(ull a, ull b) {
    ull r; asm("add.rn.f32x2 %0, %1, %2;" : "=l"(r) : "l"(a), "l"(b)); return r;
}
__device__ __forceinline__ float2 up2(ull v) {
    float2 r; asm("mov.b64 {%0, %1}, %2;" : "=f"(r.x), "=f"(r.y) : "l"(v)); return r;
}
union F4U { float4 f; ull u[2]; };

__device__ __forceinline__ float tanh_fast(float x) {
    float r; asm("tanh.approx.f32 %0, %1;" : "=f"(r) : "f"(x)); return r;
}

// ---------------- 2-vertex shared helpers ----------------
// streaming epilogue: acc pair (pre-tanh) -> tanh[/BN] -> float2 store to h
// slot -> fused fw-GEMM accumulate (weights LDS shared across the 2 vertices)
template<bool BN>
__device__ __forceinline__ void stream_epi_fw2(
    ull acc0[16], ull acc1[16],
    const float* __restrict__ sscale, const float* __restrict__ sshift,
    const float (*__restrict__ sWfw)[NC], const float* __restrict__ sbfw,
    float* __restrict__ ob, ull facc0[12], ull facc1[12])
{
    #pragma unroll
    for (int j = 0; j < 12; j++) {
        float2 bb = *(const float2*)&sbfw[2 * j];
        ull p = pk2(bb.x, bb.y);
        facc0[j] = p; facc1[j] = p;
    }
    #pragma unroll
    for (int j2 = 0; j2 < 16; j2++) {
        float2 z0 = up2(acc0[j2]), z1 = up2(acc1[j2]);
        float a00 = tanh_fast(z0.x), a01 = tanh_fast(z0.y);
        float a10 = tanh_fast(z1.x), a11 = tanh_fast(z1.y);
        if (BN) {
            float sc0 = sscale[2 * j2], sh0 = sshift[2 * j2];
            float sc1 = sscale[2 * j2 + 1], sh1 = sshift[2 * j2 + 1];
            a00 = a00 * sc0 + sh0; a10 = a10 * sc0 + sh0;
            a01 = a01 * sc1 + sh1; a11 = a11 * sc1 + sh1;
        }
        *(float2*)(ob + (size_t)(2 * j2) * NV)     = make_float2(a00, a10);
        *(float2*)(ob + (size_t)(2 * j2 + 1) * NV) = make_float2(a01, a11);
        ull d00 = dup2(a00), d01 = dup2(a01), d10 = dup2(a10), d11 = dup2(a11);
        #pragma unroll
        for (int g6 = 0; g6 < 6; g6++) {
            F4U w0; w0.f = *(const float4*)&sWfw[2 * j2][g6 * 4];
            F4U w1; w1.f = *(const float4*)&sWfw[2 * j2 + 1][g6 * 4];
            fma2(facc0[2 * g6],     d00, w0.u[0]); fma2(facc0[2 * g6 + 1], d00, w0.u[1]);
            fma2(facc0[2 * g6],     d01, w1.u[0]); fma2(facc0[2 * g6 + 1], d01, w1.u[1]);
            fma2(facc1[2 * g6],     d10, w0.u[0]); fma2(facc1[2 * g6 + 1], d10, w0.u[1]);
            fma2(facc1[2 * g6],     d11, w1.u[0]); fma2(facc1[2 * g6 + 1], d11, w1.u[1]);
        }
    }
}

__device__ __forceinline__ void fw_finish2(
    ull facc0[12], ull facc1[12], float (*__restrict__ sbuf)[HALF_V], int tid,
    float* __restrict__ gw)
{
    #pragma unroll
    for (int j = 0; j < 10; j++) {
        float2 f0 = up2(facc0[j]), f1 = up2(facc1[j]);
        *(float2*)&sbuf[2 * j][2 * tid]     = make_float2(f0.x, f1.x);
        *(float2*)&sbuf[2 * j + 1][2 * tid] = make_float2(f0.y, f1.y);
    }
    float2 p0 = up2(facc0[10]), q0 = up2(facc0[11]);
    float2 p1 = up2(facc1[10]), q1 = up2(facc1[11]);
    float w0a = __expf(-fabsf(p0.x)), w0b = __expf(-fabsf(p0.y));
    float w0c = __expf(-fabsf(q0.x)), w0d = __expf(-fabsf(q0.y));
    float w1a = __expf(-fabsf(p1.x)), w1b = __expf(-fabsf(p1.y));
    float w1c = __expf(-fabsf(q1.x)), w1d = __expf(-fabsf(q1.y));
    *(float2*)&sbuf[20][2 * tid] = make_float2(w0a, w1a);
    *(float2*)&sbuf[21][2 * tid] = make_float2(w0b, w1b);
    *(float2*)&sbuf[22][2 * tid] = make_float2(w0c, w1c);
    *(float2*)&sbuf[23][2 * tid] = make_float2(w0d, w1d);
    *(float2*)(gw)                    = make_float2(w0a, w1a);
    *(float2*)(gw + (size_t)NV)       = make_float2(w0b, w1b);
    *(float2*)(gw + (size_t)2 * NV)   = make_float2(w0c, w1c);
    *(float2*)(gw + (size_t)3 * NV)   = make_float2(w0d, w1d);
}

// 96 max/sum tasks over 512 vertices; warp w -> aa = w>>1, c = (w&1)*12..+12
__device__ __forceinline__ void reduce96_2(
    const float (*__restrict__ sbuf)[HALF_V], int b, int half, int warp, int lane,
    int pb)
{
    const int aa = warp >> 1, cbase = (warp & 1) * 12;
    ull s2[12]; float m0[12], m1[12];
    #pragma unroll
    for (int c = 0; c < 12; c++) { s2[c] = 0ull; m0[c] = -CUDART_INF_F; m1[c] = -CUDART_INF_F; }
    #pragma unroll
    for (int i = 0; i < 8; i++) {
        const int vv = (lane + i * 32) * 2;
        ull w2 = *(const ull*)&sbuf[NP + aa][vv];
        #pragma unroll
        for (int c = 0; c < 12; c++) {
            ull f2 = *(const ull*)&sbuf[cbase + c][vv];
            ull p = mul2(w2, f2);
            s2[c] = add2(s2[c], p);
            float2 pv = up2(p);
            m0[c] = fmaxf(m0[c], pv.x);
            m1[c] = fmaxf(m1[c], pv.y);
        }
    }
    #pragma unroll
    for (int c = 0; c < 12; c++) {
        float m = fmaxf(m0[c], m1[c]);
        float2 sv = up2(s2[c]);
        float s = sv.x + sv.y;
        #pragma unroll
        for (int o = 16; o > 0; o >>= 1) {
            m = fmaxf(m, __shfl_xor_sync(~0u, m, o));
            s += __shfl_xor_sync(~0u, s, o);
        }
        if (lane == 0) {
            const int t = aa * 24 + cbase + c;
            g_pmax[pb][(b * 96 + t) * 2 + half] = m;
            g_psum[pb][(b * 96 + t) * 2 + half] = s;
        }
    }
}

// =====================================================================
// kA: per-event vertex mean + folded constant bias
// =====================================================================
__global__ __launch_bounds__(256)
void kA(const float* __restrict__ x,
        const float* __restrict__ bn0_gamma, const float* __restrict__ bn0_beta,
        const float* __restrict__ bn0_mean,  const float* __restrict__ bn0_var,
        const float* __restrict__ W_in,      const float* __restrict__ b_in)
{
    __shared__ float sp[8][NFEAT];
    __shared__ float smean[NFEAT];
    __shared__ float ss0[20], st0[20];
    const int tid = threadIdx.x, b = blockIdx.x;
    const int lane = tid & 31, warp = tid >> 5;

    float s[NFEAT];
    #pragma unroll
    for (int c = 0; c < NFEAT; c++) s[c] = 0.0f;
    #pragma unroll
    for (int i = 0; i < 4; i++) {
        const float* xv = x + ((size_t)b * NV + tid + i * 256) * NFEAT;
        #pragma unroll
        for (int c = 0; c < NFEAT; c++) s[c] += xv[c];
    }
    #pragma unroll
    for (int o = 16; o > 0; o >>= 1)
        #pragma unroll
        for (int c = 0; c < NFEAT; c++) s[c] += __shfl_xor_sync(~0u, s[c], o);
    if (lane == 0)
        #pragma unroll
        for (int c = 0; c < NFEAT; c++) sp[warp][c] = s[c];
    if (tid < 20) {
        float sc = bn0_gamma[tid] * rsqrtf(bn0_var[tid] + 1e-3f);
        ss0[tid] = sc;
        st0[tid] = bn0_beta[tid] - bn0_mean[tid] * sc;
    }
    __syncthreads();
    if (tid < NFEAT) {
        float a = 0.0f;
        #pragma unroll
        for (int w = 0; w < 8; w++) a += sp[w][tid];
        smean[tid] = a * (1.0f / 1024.0f);
    }
    __syncthreads();
    if (tid < NF) {
        float a = b_in[tid];
        #pragma unroll
        for (int c = 10; c < 20; c++) {
            float g = smean[c - 10] * ss0[c] + st0[c];
            a += g * W_in[c * NF + tid];
        }
        g_cbias[b * NF + tid] = a;
    }
}

// =====================================================================
// kB_fw: h0 = tanh(bn0(x)@W_in + cbias) -> slot 0, fused fw(block 0)
// grid 256 (b=blk>>1, half=blk&1), 256 threads, 2 vertices/thread
// =====================================================================
struct __align__(16) SmemB {
    float sbuf[NC][HALF_V];
    float sW[NFEAT][NF];
    float sWfw[NF][NC];
    float scb[NF];
    float ss0[NFEAT], st0[NFEAT];
    float sbfw[NC];
};

__global__ __launch_bounds__(256, 2)
void kB_fw(const float* __restrict__ x,
           const float* __restrict__ bn0_gamma, const float* __restrict__ bn0_var,
           const float* __restrict__ bn0_beta,  const float* __restrict__ bn0_mean,
           const float* __restrict__ W_in,
           const float* __restrict__ W_flr, const float* __restrict__ b_flr,
           const float* __restrict__ W_s,   const float* __restrict__ b_s)
{
    extern __shared__ char smraw[];
    SmemB& S = *reinterpret_cast<SmemB*>(smraw);
    const int tid = threadIdx.x;
    const int b = blockIdx.x >> 1, half = blockIdx.x & 1;
    const int v0 = half * HALF_V + tid * 2;
    const int warp = tid >> 5, lane = tid & 31;

    const float* xv0 = x + ((size_t)b * NV + v0) * NFEAT;
    float xr0[NFEAT], xr1[NFEAT];
    #pragma unroll
    for (int c = 0; c < NFEAT; c++) { xr0[c] = xv0[c]; xr1[c] = xv0[NFEAT + c]; }

    for (int i = tid; i < NFEAT * NF; i += 256) S.sW[i / NF][i % NF] = W_in[i];
    for (int i = tid; i < NF * NC; i += 256) {
        int k = i / NC, c = i % NC;
        S.sWfw[k][c] = (c < NP) ? W_flr[(size_t)k * NP + c] : W_s[(size_t)k * NA + (c - NP)];
    }
    if (tid < NF) S.scb[tid] = g_cbias[b * NF + tid];
    if (tid >= 32 && tid < 32 + NFEAT) {
        int c = tid - 32;
        float sc = bn0_gamma[c] * rsqrtf(bn0_var[c] + 1e-3f);
        S.ss0[c] = sc;
        S.st0[c] = bn0_beta[c] - bn0_mean[c] * sc;
    }
    if (tid >= 64 && tid < 64 + NC)
        S.sbfw[tid - 64] = (tid - 64 < NP) ? b_flr[tid - 64] : b_s[tid - 64 - NP];
    __syncthreads();

    ull acc0[16], acc1[16];
    #pragma unroll
    for (int j = 0; j < 16; j++) {
        float2 bb = *(const float2*)&S.scb[2 * j];
        ull p = pk2(bb.x, bb.y);
        acc0[j] = p; acc1[j] = p;
    }
    #pragma unroll
    for (int c = 0; c < NFEAT; c++) {
        float sc = S.ss0[c], sh = S.st0[c];
        ull g0 = dup2(xr0[c] * sc + sh);
        ull g1 = dup2(xr1[c] * sc + sh);
        #pragma unroll
        for (int g8 = 0; g8 < 8; g8++) {
            F4U w; w.f = *(const float4*)&S.sW[c][g8 * 4];
            fma2(acc0[g8 * 2],     g0, w.u[0]); fma2(acc0[g8 * 2 + 1], g0, w.u[1]);
            fma2(acc1[g8 * 2],     g1, w.u[0]); fma2(acc1[g8 * 2 + 1], g1, w.u[1]);
        }
    }
    float* ob = g_h + (size_t)b * 384 * NV + v0;
    ull facc0[12], facc1[12];
    stream_epi_fw2<false>(acc0, acc1, nullptr, nullptr, S.sWfw, S.sbfw, ob, facc0, facc1);
    fw_finish2(facc0, facc1, S.sbuf, tid, g_w + ((size_t)b * NA) * NV + v0);
    __syncthreads();
    reduce96_2(S.sbuf, b, half, warp, lane, 0);
}

// =====================================================================
// F: fused block: Gp(l) -> out(l) -> h_{l+1} -> fw(l+1) -> partials
// grid 256 (b=blk>>1, half=blk&1), 256 threads, 2 vertices/thread
// =====================================================================
struct __align__(16) SmemF {
    float sbuf[NC][HALF_V];
    float sWo32[NF][NF];
    float sWfw[NF][NC];
    float sGp[NA][NF];
    float sam[96], sas[96];
    float sbfw[NC];
    float sbo[NF], sscale[NF], sshift[NF];
};

__global__ __launch_bounds__(256, 2)
void F_block(int l,
             const float* __restrict__ W_out,    const float* __restrict__ b_out,
             const float* __restrict__ bn_gamma, const float* __restrict__ bn_beta,
             const float* __restrict__ bn_mean,  const float* __restrict__ bn_var,
             const float* __restrict__ W_flr,    const float* __restrict__ b_flr,
             const float* __restrict__ W_s,      const float* __restrict__ b_s)
{
    extern __shared__ char smraw[];
    SmemF& S = *reinterpret_cast<SmemF*>(smraw);
    const int tid = threadIdx.x;
    const int b = blockIdx.x >> 1, half = blockIdx.x & 1;
    const int v0 = half * HALF_V + tid * 2;
    const int warp = tid >> 5, lane = tid & 31;
    const int pb = l & 1, lf = l + 1;

    const float* hb = g_h + ((size_t)b * 384 + (size_t)l * NF) * NV + v0;
    float2 wv[NA];
    #pragma unroll
    for (int a = 0; a < NA; a++)
        wv[a] = *(const float2*)(g_w + ((size_t)b * NA + a) * NV + v0);

    const float* WoG = W_out + (size_t)l * 228 * NF;
    ((float4*)&S.sWo32[0][0])[tid] = ((const float4*)WoG)[tid];   // 256 float4 = 32x32
    for (int i = tid; i < NF * NC; i += 256) {
        int k = i / NC, c = i % NC;
        S.sWfw[k][c] = (c < NP) ? W_flr[((size_t)lf * NF + k) * NP + c]
                                : W_s[((size_t)lf * NF + k) * NA + (c - NP)];
    }
    if (tid < 96) {
        float2 pm = *(const float2*)&g_pmax[pb][(b * 96 + tid) * 2];
        float2 ps = *(const float2*)&g_psum[pb][(b * 96 + tid) * 2];
        S.sam[tid] = fmaxf(pm.x, pm.y);
        S.sas[tid] = (ps.x + ps.y) * (1.0f / 1024.0f);
    }
    if (tid >= 128 && tid < 160) {
        int j = tid - 128;
        S.sbo[j] = b_out[l * NF + j];
        float sc = bn_gamma[l * NF + j] * rsqrtf(bn_var[l * NF + j] + 1e-3f);
        S.sscale[j] = sc;
        S.sshift[j] = bn_beta[l * NF + j] - bn_mean[l * NF + j] * sc;
    }
    if (tid >= 160 && tid < 160 + NC)
        S.sbfw[tid - 160] = (tid - 160 < NP) ? b_flr[lf * NP + tid - 160]
                                             : b_s[lf * NA + tid - 160 - NP];
    __syncthreads();

    if (tid < 128) {
        const int aa = warp, j = lane;
        float g = WoG[(224 + aa) * NF + j];
        #pragma unroll
        for (int c = 0; c < NC; c++)
            g += S.sam[aa * NC + c] * WoG[(32 + aa * 48 + c) * NF + j];
        #pragma unroll
        for (int c = 0; c < NC; c++)
            g += S.sas[aa * NC + c] * WoG[(32 + aa * 48 + NC + c) * NF + j];
        S.sGp[aa][j] = g;
    }
    __syncthreads();

    // out-GEMM for vertex pair; weight LDS shared
    ull acc0[16], acc1[16];
    #pragma unroll
    for (int j = 0; j < 16; j++) {
        float2 bb = *(const float2*)&S.sbo[2 * j];
        ull p = pk2(bb.x, bb.y);
        acc0[j] = p; acc1[j] = p;
    }
    #pragma unroll
    for (int kc = 0; kc < 4; kc++) {
        float2 h2[8];
        #pragma unroll
        for (int k = 0; k < 8; k++)
            h2[k] = *(const float2*)(hb + (size_t)(kc * 8 + k) * NV);
        #pragma unroll
        for (int k = 0; k < 8; k++) {
            ull hk0 = dup2(h2[k].x), hk1 = dup2(h2[k].y);
            #pragma unroll
            for (int g8 = 0; g8 < 8; g8++) {
                F4U w; w.f = *(const float4*)&S.sWo32[kc * 8 + k][g8 * 4];
                fma2(acc0[g8 * 2],     hk0, w.u[0]); fma2(acc0[g8 * 2 + 1], hk0, w.u[1]);
                fma2(acc1[g8 * 2],     hk1, w.u[0]); fma2(acc1[g8 * 2 + 1], hk1, w.u[1]);
            }
        }
    }
    #pragma unroll
    for (int a = 0; a < NA; a++) {
        ull wa0 = dup2(wv[a].x), wa1 = dup2(wv[a].y);
        #pragma unroll
        for (int g8 = 0; g8 < 8; g8++) {
            F4U gg; gg.f = *(const float4*)&S.sGp[a][g8 * 4];
            fma2(acc0[g8 * 2],     wa0, gg.u[0]); fma2(acc0[g8 * 2 + 1], wa0, gg.u[1]);
            fma2(acc1[g8 * 2],     wa1, gg.u[0]); fma2(acc1[g8 * 2 + 1], wa1, gg.u[1]);
        }
    }

    float* ob = g_h + ((size_t)b * 384 + (size_t)lf * NF) * NV + v0;
    ull facc0[12], facc1[12];
    stream_epi_fw2<true>(acc0, acc1, S.sscale, S.sshift, S.sWfw, S.sbfw, ob, facc0, facc1);
    fw_finish2(facc0, facc1, S.sbuf, tid, g_w + ((size_t)b * NA) * NV + v0);
    __syncthreads();
    reduce96_2(S.sbuf, b, half, warp, lane, pb ^ 1);
}

// =====================================================================
// G: final block (l=10): out only. writes slot 11. 2 vertices/thread
// =====================================================================
__global__ __launch_bounds__(256, 2)
void G_block(const float* __restrict__ W_out,    const float* __restrict__ b_out,
             const float* __restrict__ bn_gamma, const float* __restrict__ bn_beta,
             const float* __restrict__ bn_mean,  const float* __restrict__ bn_var)
{
    __shared__ float sWo32[NF][NF];
    __shared__ float sGp[NA][NF];
    __shared__ float sam[96], sas[96];
    __shared__ float sbo[NF], sscale[NF], sshift[NF];
    const int tid = threadIdx.x;
    const int b = blockIdx.x >> 1, half = blockIdx.x & 1;
    const int v0 = half * HALF_V + tid * 2;
    const int warp = tid >> 5, lane = tid & 31;
    const int l = 10, pb = 0;

    const float* hb = g_h + ((size_t)b * 384 + (size_t)l * NF) * NV + v0;
    float2 wv[NA];
    #pragma unroll
    for (int a = 0; a < NA; a++)
        wv[a] = *(const float2*)(g_w + ((size_t)b * NA + a) * NV + v0);

    const float* WoG = W_out + (size_t)l * 228 * NF;
    ((float4*)&sWo32[0][0])[tid] = ((const float4*)WoG)[tid];
    if (tid < 96) {
        float2 pm = *(const float2*)&g_pmax[pb][(b * 96 + tid) * 2];
        float2 ps = *(const float2*)&g_psum[pb][(b * 96 + tid) * 2];
        sam[tid] = fmaxf(pm.x, pm.y);
        sas[tid] = (ps.x + ps.y) * (1.0f / 1024.0f);
    }
    if (tid >= 128 && tid < 160) {
        int j = tid - 128;
        sbo[j] = b_out[l * NF + j];
        float sc = bn_gamma[l * NF + j] * rsqrtf(bn_var[l * NF + j] + 1e-3f);
        sscale[j] = sc;
        sshift[j] = bn_beta[l * NF + j] - bn_mean[l * NF + j] * sc;
    }
    __syncthreads();
    if (tid < 128) {
        const int aa = warp, j = lane;
        float g = WoG[(224 + aa) * NF + j];
        #pragma unroll
        for (int c = 0; c < NC; c++)
            g += sam[aa * NC + c] * WoG[(32 + aa * 48 + c) * NF + j];
        #pragma unroll
        for (int c = 0; c < NC; c++)
            g += sas[aa * NC + c] * WoG[(32 + aa * 48 + NC + c) * NF + j];
        sGp[aa][j] = g;
    }
    __syncthreads();

    ull acc0[16], acc1[16];
    #pragma unroll
    for (int j = 0; j < 16; j++) {
        float2 bb = *(const float2*)&sbo[2 * j];
        ull p = pk2(bb.x, bb.y);
        acc0[j] = p; acc1[j] = p;
    }
    #pragma unroll
    for (int kc = 0; kc < 4; kc++) {
        float2 h2[8];
        #pragma unroll
        for (int k = 0; k < 8; k++)
            h2[k] = *(const float2*)(hb + (size_t)(kc * 8 + k) * NV);
        #pragma unroll
        for (int k = 0; k < 8; k++) {
            ull hk0 = dup2(h2[k].x), hk1 = dup2(h2[k].y);
            #pragma unroll
            for (int g8 = 0; g8 < 8; g8++) {
                F4U w; w.f = *(const float4*)&sWo32[kc * 8 + k][g8 * 4];
                fma2(acc0[g8 * 2],     hk0, w.u[0]); fma2(acc0[g8 * 2 + 1], hk0, w.u[1]);
                fma2(acc1[g8 * 2],     hk1, w.u[0]); fma2(acc1[g8 * 2 + 1], hk1, w.u[1]);
            }
        }
    }
    #pragma unroll
    for (int a = 0; a < NA; a++) {
        ull wa0 = dup2(wv[a].x), wa1 = dup2(wv[a].y);
        #pragma unroll
        for (int g8 = 0; g8 < 8; g8++) {
            F4U gg; gg.f = *(const float4*)&sGp[a][g8 * 4];
            fma2(acc0[g8 * 2],     wa0, gg.u[0]); fma2(acc0[g8 * 2 + 1], wa0, gg.u[1]);
            fma2(acc1[g8 * 2],     wa1, gg.u[0]); fma2(acc1[g8 * 2 + 1], wa1, gg.u[1]);
        }
    }
    float* ob = g_h + ((size_t)b * 384 + (size_t)11 * NF) * NV + v0;
    #pragma unroll
    for (int j2 = 0; j2 < 16; j2++) {
        float2 z0 = up2(acc0[j2]), z1 = up2(acc1[j2]);
        float sc0 = sscale[2 * j2], sh0 = sshift[2 * j2];
        float sc1 = sscale[2 * j2 + 1], sh1 = sshift[2 * j2 + 1];
        *(float2*)(ob + (size_t)(2 * j2) * NV) =
            make_float2(tanh_fast(z0.x) * sc0 + sh0, tanh_fast(z1.x) * sc0 + sh0);
        *(float2*)(ob + (size_t)(2 * j2 + 1) * NV) =
            make_float2(tanh_fast(z0.y) * sc1 + sh1, tanh_fast(z1.y) * sc1 + sh1);
    }
}

// =====================================================================
// k2: out = relu(relu(feats @ W_o0 + b_o0) @ W_o1 + b_o1); feats = slots 1..11
// =====================================================================
#define K2_SMEMF (DFE * 48 + 144 + 48 + 4)

__global__ __launch_bounds__(256, 2)
void k2_mlp(const float* __restrict__ W_o0, const float* __restrict__ b_o0,
            const float* __restrict__ W_o1, const float* __restrict__ b_o1,
            float* __restrict__ out)
{
    extern __shared__ float s2[];
    float* Ws  = s2;
    float* sW1 = s2 + DFE * 48;
    float* sb0 = sW1 + 144;
    float* sb1 = sb0 + 48;
    const int tid = threadIdx.x;
    {
        const float4* src = (const float4*)W_o0;
        float4* dst = (float4*)Ws;
        for (int i = tid; i < DFE * 48 / 4; i += 256) dst[i] = src[i];
    }
    if (tid < 144) sW1[tid] = W_o1[tid];
    if (tid < 48)  sb0[tid] = b_o0[tid];
    if (tid < 3)   sb1[tid] = b_o1[tid];
    __syncthreads();

    const int b = blockIdx.x >> 1, half = blockIdx.x & 1;
    const int v0 = half * 512 + tid * 2;

    ull acc0[24], acc1[24];
    #pragma unroll
    for (int j = 0; j < 24; j++) {
        float2 bb = *(const float2*)&sb0[2 * j];
        ull p = pk2(bb.x, bb.y);
        acc0[j] = p; acc1[j] = p;
    }
    const float* fb = g_h + ((size_t)b * 384 + NF) * NV + v0;
    #pragma unroll 4
    for (int k = 0; k < DFE; k++) {
        float2 f = *(const float2*)(fb + (size_t)k * NV);
        ull f0 = dup2(f.x), f1 = dup2(f.y);
        #pragma unroll
        for (int g12 = 0; g12 < 12; g12++) {
            F4U w; w.f = *(const float4*)&Ws[k * 48 + g12 * 4];
            fma2(acc0[g12 * 2],     f0, w.u[0]);
            fma2(acc0[g12 * 2 + 1], f0, w.u[1]);
            fma2(acc1[g12 * 2],     f1, w.u[0]);
            fma2(acc1[g12 * 2 + 1], f1, w.u[1]);
        }
    }
    #pragma unroll
    for (int m = 0; m < 2; m++) {
        const ull* acc = m ? acc1 : acc0;
        float o0 = sb1[0], o1 = sb1[1], o2 = sb1[2];
        #pragma unroll
        for (int j2 = 0; j2 < 24; j2++) {
            float2 hv = up2(acc[j2]);
            float a = fmaxf(hv.x, 0.0f), c = fmaxf(hv.y, 0.0f);
            o0 += a * sW1[(2 * j2) * 3 + 0] + c * sW1[(2 * j2 + 1) * 3 + 0];
            o1 += a * sW1[(2 * j2) * 3 + 1] + c * sW1[(2 * j2 + 1) * 3 + 1];
            o2 += a * sW1[(2 * j2) * 3 + 2] + c * sW1[(2 * j2 + 1) * 3 + 2];
        }
        float* op = out + ((size_t)b * NV + v0 + m) * 3;
        op[0] = fmaxf(o0, 0.0f);
        op[1] = fmaxf(o1, 0.0f);
        op[2] = fmaxf(o2, 0.0f);
    }
}

// =====================================================================
extern "C" void kernel_launch(void* const* d_in, const int* in_sizes, int n_in,
                              void* d_out, int out_size)
{
    const float* x         = (const float*)d_in[0];
    const float* bn0_gamma = (const float*)d_in[1];
    const float* bn0_beta  = (const float*)d_in[2];
    const float* bn0_mean  = (const float*)d_in[3];
    const float* bn0_var   = (const float*)d_in[4];
    const float* W_in      = (const float*)d_in[5];
    const float* b_in      = (const float*)d_in[6];
    const float* W_flr     = (const float*)d_in[7];
    const float* b_flr     = (const float*)d_in[8];
    const float* W_s       = (const float*)d_in[9];
    const float* b_s       = (const float*)d_in[10];
    const float* W_out     = (const float*)d_in[11];
    const float* b_out     = (const float*)d_in[12];
    const float* bn_gamma  = (const float*)d_in[13];
    const float* bn_beta   = (const float*)d_in[14];
    const float* bn_mean   = (const float*)d_in[15];
    const float* bn_var    = (const float*)d_in[16];
    const float* W_o0      = (const float*)d_in[17];
    const float* b_o0      = (const float*)d_in[18];
    const float* W_o1      = (const float*)d_in[19];
    const float* b_o1      = (const float*)d_in[20];

    cudaFuncSetAttribute(kB_fw, cudaFuncAttributeMaxDynamicSharedMemorySize,
                         (int)sizeof(SmemB));
    cudaFuncSetAttribute(F_block, cudaFuncAttributeMaxDynamicSharedMemorySize,
                         (int)sizeof(SmemF));
    cudaFuncSetAttribute(k2_mlp, cudaFuncAttributeMaxDynamicSharedMemorySize,
                         (int)(K2_SMEMF * sizeof(float)));

    kA<<<NB, 256>>>(x, bn0_gamma, bn0_beta, bn0_mean, bn0_var, W_in, b_in);
    kB_fw<<<NB * 2, 256, sizeof(SmemB)>>>(x, bn0_gamma, bn0_var, bn0_beta, bn0_mean,
                                          W_in, W_flr, b_flr, W_s, b_s);

    for (int l = 0; l < NBK - 1; l++) {
        F_block<<<NB * 2, 256, sizeof(SmemF)>>>(l, W_out, b_out, bn_gamma, bn_beta,
                                                bn_mean, bn_var, W_flr, b_flr, W_s, b_s);
    }
    G_block<<<NB * 2, 256>>>(W_out, b_out, bn_gamma, bn_beta, bn_mean, bn_var);

    k2_mlp<<<NB * 2, 256, K2_SMEMF * sizeof(float)>>>(
        W_o0, b_o0, W_o1, b_o1, (float*)d_out);
}